// round 1
// baseline (speedup 1.0000x reference)
#include <cuda_runtime.h>
#include <cstdint>

#define INW    128
#define OUTW   128
#define BATCHN 128
#define T_TAB  (INW * OUTW)   // 16384
#define KTAPS  4
#define KKC    16
#define NLEV   2

// Scratch (allocation-free rule: __device__ globals)
__device__ float g_W[T_TAB * 32];        // [t][l*16+g]  (2 MB)
__device__ uint4 g_signs[NLEV][BATCHN];  // 128-bit sign mask per (level, batch)

// ---------------------------------------------------------------------------
// Kernel 1: sign bitmasks.  grid=128 (batch), block=128 (input)
// ---------------------------------------------------------------------------
__global__ void sign_kernel(const float* __restrict__ x,
                            const float* __restrict__ means) {
    int b = blockIdx.x;
    int i = threadIdx.x;          // 0..127
    float a0 = fabsf(means[0]);
    float v  = x[b * INW + i];
    bool s0  = (v >= 0.0f);
    float r  = v - (s0 ? a0 : -a0);
    bool s1  = (r >= 0.0f);
    unsigned m0 = __ballot_sync(0xffffffffu, s0);
    unsigned m1 = __ballot_sync(0xffffffffu, s1);
    int w = i >> 5;
    if ((i & 31) == 0) {
        ((unsigned*)&g_signs[0][b])[w] = m0;
        ((unsigned*)&g_signs[1][b])[w] = m1;
    }
}

// ---------------------------------------------------------------------------
// Kernel 2: collapsed LUT table  W[t][l][g] = sum_c w[t,c] * P_l[popc(c^g)]
// grid = T/16 = 1024, block = 512 (16 tables x 32 (l,g) entries)
// ---------------------------------------------------------------------------
__global__ void __launch_bounds__(512) wtab_kernel(const float* __restrict__ weight,
                                                   const float* __restrict__ means) {
    __shared__ float sw[16 * KKC];
    int tlocal = threadIdx.x >> 5;       // 0..15
    int lg     = threadIdx.x & 31;       // l*16+g
    int l      = lg >> 4;
    int g      = lg & 15;
    int tbase  = blockIdx.x * 16;

    for (int j = threadIdx.x; j < 16 * KKC; j += blockDim.x)
        sw[j] = weight[tbase * KKC + j];
    __syncthreads();

    float a = fabsf(means[l]);
    float p = 0.5f * (1.0f + a);
    float m = 0.5f * (1.0f - a);
    float P[KTAPS + 1];
    P[0] = p * p * p * p;
    P[1] = p * p * p * m;
    P[2] = p * p * m * m;
    P[3] = p * m * m * m;
    P[4] = m * m * m * m;

    float acc = 0.0f;
#pragma unroll
    for (int c = 0; c < KKC; c++)
        acc += sw[tlocal * KKC + c] * P[__popc(c ^ g)];

    g_W[(tbase + tlocal) * 32 + lg] = acc;
}

// ---------------------------------------------------------------------------
// Kernel 3: main gather + accumulate.
// grid = 128 (o), block = 512 = 4 i-slices x 128 batches.
// ---------------------------------------------------------------------------
__device__ __forceinline__ unsigned bitof(const uint4& S, int idx) {
    unsigned w = (idx & 64) ? ((idx & 32) ? S.w : S.z)
                            : ((idx & 32) ? S.y : S.x);
    return (w >> (idx & 31)) & 1u;
}

__global__ void __launch_bounds__(512) main_kernel(const float* __restrict__ bias,
                                                   const int*   __restrict__ mask,
                                                   float*       __restrict__ out) {
    __shared__ float sW[INW * 32];   // 16 KB: this o's 128 tables x 32 entries
    __shared__ int4  sIdx[INW];      // 2 KB : 4 taps per table
    __shared__ float red[512];

    int o   = blockIdx.x;
    int tid = threadIdx.x;
    int b   = tid & 127;
    int s   = tid >> 7;              // 0..3 i-slice

    // Stage LUT slice and indices
    const float4* gW4 = (const float4*)&g_W[o * (INW * 32)];
    float4* sW4 = (float4*)sW;
    for (int j = tid; j < INW * 32 / 4; j += 512) sW4[j] = gW4[j];
    const int4* gm4 = ((const int4*)mask) + o * INW;
    for (int j = tid; j < INW; j += 512) sIdx[j] = gm4[j];
    __syncthreads();

    uint4 S0 = g_signs[0][b];
    uint4 S1 = g_signs[1][b];

    float acc = 0.0f;
#pragma unroll 4
    for (int i = s; i < INW; i += 4) {
        int4 id = sIdx[i];
        unsigned g0 =  bitof(S0, id.x)
                    | (bitof(S0, id.y) << 1)
                    | (bitof(S0, id.z) << 2)
                    | (bitof(S0, id.w) << 3);
        unsigned g1 =  bitof(S1, id.x)
                    | (bitof(S1, id.y) << 1)
                    | (bitof(S1, id.z) << 2)
                    | (bitof(S1, id.w) << 3);
        acc += sW[i * 32 + g0] + sW[i * 32 + 16 + g1];
    }

    red[tid] = acc;
    __syncthreads();
    if (s == 0) {
        float tot = red[b] + red[b + 128] + red[b + 256] + red[b + 384] + bias[o];
        out[b * OUTW + o] = tot;
    }
}

// ---------------------------------------------------------------------------
extern "C" void kernel_launch(void* const* d_in, const int* in_sizes, int n_in,
                              void* d_out, int out_size) {
    const float* x      = (const float*)d_in[0];
    const float* weight = (const float*)d_in[1];
    const float* bias   = (const float*)d_in[2];
    const float* means  = (const float*)d_in[3];
    const int*   mask   = (const int*)  d_in[4];
    float* out = (float*)d_out;

    sign_kernel<<<BATCHN, INW>>>(x, means);
    wtab_kernel<<<T_TAB / 16, 512>>>(weight, means);
    main_kernel<<<OUTW, 512>>>(bias, mask, out);
}

// round 2
// speedup vs baseline: 2.4322x; 2.4322x over previous
#include <cuda_runtime.h>
#include <cstdint>

#define INW    128
#define OUTW   128
#define BATCHN 128

// One fully-fused kernel: grid = 128 (one block per output o), block = 512.
//  - builds sign bytes for all (input, batch) pairs:  s0 | s1<<4
//  - builds this o's collapsed LUT W[i][l][g] via fast Walsh-Hadamard transform
//  - gathers 4-bit codes per (batch, table) and accumulates 2 SMEM lookups each
__global__ void __launch_bounds__(512, 1) fused_kernel(
    const float* __restrict__ x,
    const float* __restrict__ weight,
    const float* __restrict__ bias,
    const float* __restrict__ means,
    const int*   __restrict__ mask,
    float*       __restrict__ out)
{
    __shared__ float         sW[INW * 33];      // [i]: 16 (level0) + 16 (level1), row pad 33
    __shared__ unsigned char sSB[INW * 132];    // [i][b] byte = s0 | s1<<4, row pad 132
    __shared__ int4          sIdx[INW];         // 4 taps per table
    __shared__ float         red[512];

    const int tid = threadIdx.x;
    const int o   = blockIdx.x;

    const float a0 = fabsf(means[0]);
    const float a1 = fabsf(means[1]);

    // ---------------- sign bytes: 4096 32-bit words, 8 per thread ----------------
    #pragma unroll
    for (int j = 0; j < 8; j++) {
        int wlin = j * 512 + tid;            // [0, 4096)
        int i    = wlin & 127;               // input index  (lanes -> consecutive i: coalesced LDG)
        int b0   = (wlin >> 7) * 4;          // batch group of 4
        unsigned pack = 0;
        #pragma unroll
        for (int k = 0; k < 4; k++) {
            float v   = x[(b0 + k) * INW + i];
            bool  s0  = (v >= 0.0f);
            float thr = s0 ? a0 : -a0;
            bool  s1  = (v >= thr);
            unsigned byte = (s0 ? 1u : 0u) | (s1 ? 16u : 0u);
            pack |= byte << (k * 8);
        }
        *(unsigned*)&sSB[i * 132 + b0] = pack;   // bank = i%32 : conflict-free
    }

    // ---------------- collapsed LUT via WHT (threads 0..127) ----------------
    // W[l][g] = sum_c w[c] * prod_j (bit j of (g^c) ? (1-a_l)/2 : (1+a_l)/2)
    //         = (1/16) * WHT( WHT(w) .* a_l^{popc(S)} )
    if (tid < 128) {
        float f[16];
        const float4* wp = (const float4*)(weight + (size_t)(o * INW + tid) * 16);
        #pragma unroll
        for (int q = 0; q < 4; q++) {
            float4 v = wp[q];
            f[q*4+0] = v.x; f[q*4+1] = v.y; f[q*4+2] = v.z; f[q*4+3] = v.w;
        }
        // forward WHT (self-inverse butterfly)
        #pragma unroll
        for (int s = 1; s < 16; s <<= 1)
            #pragma unroll
            for (int i2 = 0; i2 < 16; i2++)
                if (!(i2 & s)) { float u = f[i2], v = f[i2 ^ s]; f[i2] = u + v; f[i2 ^ s] = u - v; }

        float* dst = &sW[tid * 33];
        #pragma unroll
        for (int l = 0; l < 2; l++) {
            const float a = (l == 0) ? a0 : a1;
            float pw[5];
            pw[0] = 1.0f / 16.0f;
            pw[1] = pw[0] * a; pw[2] = pw[1] * a; pw[3] = pw[2] * a; pw[4] = pw[3] * a;
            float h[16];
            #pragma unroll
            for (int i2 = 0; i2 < 16; i2++) h[i2] = f[i2] * pw[__popc(i2)];
            // inverse WHT (same butterfly)
            #pragma unroll
            for (int s = 1; s < 16; s <<= 1)
                #pragma unroll
                for (int i2 = 0; i2 < 16; i2++)
                    if (!(i2 & s)) { float u = h[i2], v = h[i2 ^ s]; h[i2] = u + v; h[i2 ^ s] = u - v; }
            #pragma unroll
            for (int i2 = 0; i2 < 16; i2++) dst[l * 16 + i2] = h[i2];  // bank = tid%32: conflict-free
        }
    } else if (tid < 256) {
        sIdx[tid - 128] = ((const int4*)mask)[o * INW + (tid - 128)];
    }
    __syncthreads();

    // ---------------- main gather + accumulate ----------------
    const int b = tid & 127;     // batch (consecutive across warp lanes)
    const int s = tid >> 7;      // i-slice 0..3
    const unsigned char* sbB = &sSB[b];

    float acc0 = 0.0f, acc1 = 0.0f;
    #pragma unroll
    for (int k = 0; k < 32; k++) {
        const int i  = s * 32 + k;
        const int4 id = sIdx[i];                 // uniform per warp: broadcast LDS
        unsigned v0 = sbB[id.x * 132];           // bytes hold s0|s1<<4
        unsigned v1 = sbB[id.y * 132];
        unsigned v2 = sbB[id.z * 132];
        unsigned v3 = sbB[id.w * 132];
        unsigned vc = (v0 + v1 * 2u) + (v2 + v3 * 2u) * 4u;  // g0 in bits 0-3, g1 in bits 4-7
        unsigned g0 = vc & 15u;
        unsigned g1 = vc >> 4;
        acc0 += sW[i * 33 + g0];
        acc1 += sW[i * 33 + 16 + g1];
    }

    red[tid] = acc0 + acc1;
    __syncthreads();
    if (s == 0) {
        float tot = red[b] + red[b + 128] + red[b + 256] + red[b + 384] + bias[o];
        out[b * OUTW + o] = tot;
    }
}

// ---------------------------------------------------------------------------
extern "C" void kernel_launch(void* const* d_in, const int* in_sizes, int n_in,
                              void* d_out, int out_size) {
    const float* x      = (const float*)d_in[0];
    const float* weight = (const float*)d_in[1];
    const float* bias   = (const float*)d_in[2];
    const float* means  = (const float*)d_in[3];
    const int*   mask   = (const int*)  d_in[4];
    float* out = (float*)d_out;

    fused_kernel<<<OUTW, 512>>>(x, weight, bias, means, mask, out);
}